// round 1
// baseline (speedup 1.0000x reference)
#include <cuda_runtime.h>

// Problem constants: q[B,H,P,D], k[B,H,P,D], scale[1] -> out[B,H,P,P] fp32
// B=4, H=16, P=1024, D=128
#define THREADS 256

constexpr int Bc = 4;
constexpr int Hc = 16;
constexpr int Pp = 1024;
constexpr int Dd = 128;

constexpr int BM  = 32;    // query rows per CTA
constexpr int TN  = 128;   // key tile
constexpr int QS  = 36;    // padded stride for QsT rows (multiple of 4 for float4 align)
constexpr int NKT = Pp / TN;  // 8 key tiles

__device__ __forceinline__ float silu_f(float x) {
    // x * sigmoid(x)
    return x * (1.0f / (1.0f + __expf(-x)));
}

__global__ void __launch_bounds__(THREADS, 1)
patch_attn_kernel(const float* __restrict__ q,
                  const float* __restrict__ kk,
                  const float* __restrict__ scale_p,
                  float*       __restrict__ out)
{
    extern __shared__ float smem[];
    float* QsT = smem;                 // [Dd][QS]   silu(Q) transposed: QsT[d][row]
    float* KsT = QsT + Dd * QS;        // [Dd][TN]   silu(K) transposed, 16B-chunk XOR swizzled
    float* S   = KsT + Dd * TN;        // [BM][Pp]   raw scores

    const int tid = threadIdx.x;
    const int tx  = tid & 31;          // lane
    const int ty  = tid >> 5;          // warp (0..7)
    const int mtile = blockIdx.x;      // 0..31
    const int bh    = blockIdx.y;      // 0..63
    const float sc  = scale_p[0];

    const float* qbase = q  + ((size_t)bh * Pp + (size_t)mtile * BM) * Dd;
    const float* kbase = kk + (size_t)bh * Pp * Dd;

    // ---- Load Q tile: silu + transpose into QsT[d][row] ----
    for (int i = tid; i < BM * Dd / 4; i += THREADS) {
        int d4  = (i & 31) << 2;       // 0..124
        int row = i >> 5;              // 0..31
        float4 v = *(const float4*)(qbase + (size_t)row * Dd + d4);
        QsT[(d4 + 0) * QS + row] = silu_f(v.x);
        QsT[(d4 + 1) * QS + row] = silu_f(v.y);
        QsT[(d4 + 2) * QS + row] = silu_f(v.z);
        QsT[(d4 + 3) * QS + row] = silu_f(v.w);
    }

    // ---- Loop over key tiles ----
    for (int kt = 0; kt < NKT; ++kt) {
        __syncthreads();  // protect KsT reuse

        // Load K tile (128 keys x 128 dims): silu + transpose with XOR swizzle.
        // Each thread handles a 4x4 (key x dim) block: coalesced gmem float4 loads
        // along d, register transpose, conflict-free STS.128 along keys.
        const float* ktb = kbase + (size_t)(kt * TN) * Dd;
        for (int i = tid; i < TN * Dd / 16; i += THREADS) {
            int d4   = (i & 31) << 2;  // dim start (0..124)
            int key4 = (i >> 5) << 2;  // key start (0..124)
            float4 r0 = *(const float4*)(ktb + (size_t)(key4 + 0) * Dd + d4);
            float4 r1 = *(const float4*)(ktb + (size_t)(key4 + 1) * Dd + d4);
            float4 r2 = *(const float4*)(ktb + (size_t)(key4 + 2) * Dd + d4);
            float4 r3 = *(const float4*)(ktb + (size_t)(key4 + 3) * Dd + d4);

            float a00 = silu_f(r0.x), a01 = silu_f(r0.y), a02 = silu_f(r0.z), a03 = silu_f(r0.w);
            float a10 = silu_f(r1.x), a11 = silu_f(r1.y), a12 = silu_f(r1.z), a13 = silu_f(r1.w);
            float a20 = silu_f(r2.x), a21 = silu_f(r2.y), a22 = silu_f(r2.z), a23 = silu_f(r2.w);
            float a30 = silu_f(r3.x), a31 = silu_f(r3.y), a32 = silu_f(r3.z), a33 = silu_f(r3.w);

            // physical 16B chunk: (key>>2) ^ (d>>2); same for all 4 dims (d4..d4+3 share d4>>2)
            int pc = (key4 >> 2) ^ (d4 >> 2);
            float* base = KsT + (pc << 2);
            *(float4*)(base + (size_t)(d4 + 0) * TN) = make_float4(a00, a10, a20, a30);
            *(float4*)(base + (size_t)(d4 + 1) * TN) = make_float4(a01, a11, a21, a31);
            *(float4*)(base + (size_t)(d4 + 2) * TN) = make_float4(a02, a12, a22, a32);
            *(float4*)(base + (size_t)(d4 + 3) * TN) = make_float4(a03, a13, a23, a33);
        }
        __syncthreads();

        // Compute 32x128 score block: acc[i][j], rows 4*ty+i, keys kt*128 + 4*tx+j
        float acc[4][4];
        #pragma unroll
        for (int i = 0; i < 4; ++i)
            #pragma unroll
            for (int j = 0; j < 4; ++j) acc[i][j] = 0.0f;

        #pragma unroll 8
        for (int kd = 0; kd < Dd; ++kd) {
            float4 a = *(const float4*)(QsT + kd * QS + (ty << 2));      // broadcast within warp
            int pc = tx ^ ((kd >> 2) & 31);                              // un-swizzle
            float4 b = *(const float4*)(KsT + kd * TN + (pc << 2));      // conflict-free

            acc[0][0] += a.x * b.x; acc[0][1] += a.x * b.y; acc[0][2] += a.x * b.z; acc[0][3] += a.x * b.w;
            acc[1][0] += a.y * b.x; acc[1][1] += a.y * b.y; acc[1][2] += a.y * b.z; acc[1][3] += a.y * b.w;
            acc[2][0] += a.z * b.x; acc[2][1] += a.z * b.y; acc[2][2] += a.z * b.z; acc[2][3] += a.z * b.w;
            acc[3][0] += a.w * b.x; acc[3][1] += a.w * b.y; acc[3][2] += a.w * b.z; acc[3][3] += a.w * b.w;
        }

        // Write raw scores to SMEM (coalesced float4, conflict-free)
        #pragma unroll
        for (int i = 0; i < 4; ++i) {
            *(float4*)(S + (size_t)((ty << 2) + i) * Pp + kt * TN + (tx << 2)) =
                make_float4(acc[i][0], acc[i][1], acc[i][2], acc[i][3]);
        }
    }
    __syncthreads();

    // ---- Fused softmax over each row of S (32 rows, 4 per warp) ----
    #pragma unroll
    for (int rr = 0; rr < 4; ++rr) {
        int row = (ty << 2) + rr;
        const float* Sr = S + (size_t)row * Pp;

        float4 vv[8];
        float m = -1e30f;
        #pragma unroll
        for (int j = 0; j < 8; ++j) {
            float4 v = *(const float4*)(Sr + (j << 7) + (tx << 2));
            vv[j] = v;
            m = fmaxf(m, fmaxf(fmaxf(v.x, v.y), fmaxf(v.z, v.w)));
        }
        #pragma unroll
        for (int o = 16; o > 0; o >>= 1) m = fmaxf(m, __shfl_xor_sync(0xFFFFFFFFu, m, o));

        float sum = 0.0f;
        #pragma unroll
        for (int j = 0; j < 8; ++j) {
            float4 v = vv[j];
            v.x = __expf(sc * (v.x - m));
            v.y = __expf(sc * (v.y - m));
            v.z = __expf(sc * (v.z - m));
            v.w = __expf(sc * (v.w - m));
            sum += (v.x + v.y) + (v.z + v.w);
            vv[j] = v;
        }
        #pragma unroll
        for (int o = 16; o > 0; o >>= 1) sum += __shfl_xor_sync(0xFFFFFFFFu, sum, o);
        float inv = 1.0f / sum;

        float* orow = out + ((size_t)bh * Pp + (size_t)mtile * BM + row) * Pp;
        #pragma unroll
        for (int j = 0; j < 8; ++j) {
            float4 v = vv[j];
            v.x *= inv; v.y *= inv; v.z *= inv; v.w *= inv;
            *(float4*)(orow + (j << 7) + (tx << 2)) = v;
        }
    }
}

extern "C" void kernel_launch(void* const* d_in, const int* in_sizes, int n_in,
                              void* d_out, int out_size)
{
    const float* q     = (const float*)d_in[0];
    const float* k     = (const float*)d_in[1];
    const float* scale = (const float*)d_in[2];
    float* out = (float*)d_out;

    const int smem_bytes = (Dd * QS + Dd * TN + BM * Pp) * (int)sizeof(float); // 215040 B
    cudaFuncSetAttribute(patch_attn_kernel,
                         cudaFuncAttributeMaxDynamicSharedMemorySize, smem_bytes);

    dim3 grid(Pp / BM, Bc * Hc);  // (32, 64)
    patch_attn_kernel<<<grid, THREADS, smem_bytes>>>(q, k, scale, out);
}

// round 3
// speedup vs baseline: 4.7842x; 4.7842x over previous
#include <cuda_runtime.h>
#include <cuda_bf16.h>
#include <stdint.h>

constexpr int Bc = 4, Hc = 16, Pp = 1024, Dd = 128;
constexpr int NELEM = Bc * Hc * Pp * Dd;       // 8388608
constexpr int BM = 32;       // query rows per CTA
constexpr int TN = 128;      // keys per tile
constexpr int NT = Pp / TN;  // 8 tiles

// ---- device scratch: silu'd q/k as bf16 hi/lo split ----
__device__ __nv_bfloat16 g_qhi[NELEM], g_qlo[NELEM], g_khi[NELEM], g_klo[NELEM];

// ---- smem layout (bytes) for pass 2 ----
constexpr int OFF_AH = 0;                 // 32 x 256B = 8192
constexpr int OFF_AL = 8192;              // 8192
constexpr int OFF_B  = 16384;             // 3 bufs x 64KB
constexpr int BBUF   = 65536;             // per buf: hi 32KB + lo 32KB
constexpr int OFF_RS = OFF_B + 3 * BBUF;  // 8 colbands x 32 rows x 4B = 1024
constexpr int OFF_INV = OFF_RS + 1024;    // 32 x 4B
constexpr int SMEM2 = OFF_INV + 128;      // 214272 B

// =================== helpers ===================
__device__ __forceinline__ uint32_t smem_u32(const void* p) {
    uint32_t a;
    asm("{ .reg .u64 t; cvta.to.shared.u64 t, %1; cvt.u32.u64 %0, t; }" : "=r"(a) : "l"(p));
    return a;
}
__device__ __forceinline__ void cpa16(uint32_t dst, const void* src) {
    asm volatile("cp.async.cg.shared.global [%0], [%1], 16;" :: "r"(dst), "l"(src));
}
__device__ __forceinline__ void cpa_commit() { asm volatile("cp.async.commit_group;" ::: "memory"); }
template<int N>
__device__ __forceinline__ void cpa_wait() { asm volatile("cp.async.wait_group %0;" :: "n"(N) : "memory"); }

__device__ __forceinline__ void ldsm4(uint32_t* r, uint32_t addr) {
    asm volatile("ldmatrix.sync.aligned.m8n8.x4.shared.b16 {%0,%1,%2,%3}, [%4];"
                 : "=r"(r[0]), "=r"(r[1]), "=r"(r[2]), "=r"(r[3]) : "r"(addr));
}
__device__ __forceinline__ void mma16816(float& d0, float& d1, float& d2, float& d3,
                                         const uint32_t* a, uint32_t b0, uint32_t b1) {
    asm volatile(
        "mma.sync.aligned.m16n8k16.row.col.f32.bf16.bf16.f32 "
        "{%0,%1,%2,%3}, {%4,%5,%6,%7}, {%8,%9}, {%0,%1,%2,%3};"
        : "+f"(d0), "+f"(d1), "+f"(d2), "+f"(d3)
        : "r"(a[0]), "r"(a[1]), "r"(a[2]), "r"(a[3]), "r"(b0), "r"(b1));
}

__device__ __forceinline__ float silu_f(float x) {
    return x * (1.0f / (1.0f + __expf(-x)));
}
__device__ __forceinline__ uint32_t pack_bf2(__nv_bfloat16 a, __nv_bfloat16 b) {
    __nv_bfloat162 t(a, b);
    return *reinterpret_cast<uint32_t*>(&t);
}

// =================== Pass 1: silu + bf16 hi/lo split ===================
__global__ void __launch_bounds__(256)
silu_split_kernel(const float* __restrict__ q, const float* __restrict__ k)
{
    int j = blockIdx.x * 256 + threadIdx.x;   // float4 group index
    float4 vq = ((const float4*)q)[j];
    float4 vk = ((const float4*)k)[j];

    float s0 = silu_f(vq.x), s1 = silu_f(vq.y), s2 = silu_f(vq.z), s3 = silu_f(vq.w);
    __nv_bfloat16 h0 = __float2bfloat16(s0), h1 = __float2bfloat16(s1),
                  h2 = __float2bfloat16(s2), h3 = __float2bfloat16(s3);
    __nv_bfloat16 l0 = __float2bfloat16(s0 - __bfloat162float(h0));
    __nv_bfloat16 l1 = __float2bfloat16(s1 - __bfloat162float(h1));
    __nv_bfloat16 l2 = __float2bfloat16(s2 - __bfloat162float(h2));
    __nv_bfloat16 l3 = __float2bfloat16(s3 - __bfloat162float(h3));
    ((uint2*)g_qhi)[j] = make_uint2(pack_bf2(h0, h1), pack_bf2(h2, h3));
    ((uint2*)g_qlo)[j] = make_uint2(pack_bf2(l0, l1), pack_bf2(l2, l3));

    s0 = silu_f(vk.x); s1 = silu_f(vk.y); s2 = silu_f(vk.z); s3 = silu_f(vk.w);
    h0 = __float2bfloat16(s0); h1 = __float2bfloat16(s1);
    h2 = __float2bfloat16(s2); h3 = __float2bfloat16(s3);
    l0 = __float2bfloat16(s0 - __bfloat162float(h0));
    l1 = __float2bfloat16(s1 - __bfloat162float(h1));
    l2 = __float2bfloat16(s2 - __bfloat162float(h2));
    l3 = __float2bfloat16(s3 - __bfloat162float(h3));
    ((uint2*)g_khi)[j] = make_uint2(pack_bf2(h0, h1), pack_bf2(h2, h3));
    ((uint2*)g_klo)[j] = make_uint2(pack_bf2(l0, l1), pack_bf2(l2, l3));
}

// =================== Pass 2: HMMA GEMM + fused softmax ===================
// 512 threads = 16 warps. Warp w: row band wb=w&1 (16 rows), col band wc=w>>1
// (16 keys of each 128-key tile). Scores live in acc[8][8] registers.
__global__ void __launch_bounds__(512, 1)
attn_mma_kernel(const float* __restrict__ scale_p, float* __restrict__ out)
{
    extern __shared__ char smem[];
    const uint32_t sb = smem_u32(smem);
    const int tid = threadIdx.x, lane = tid & 31, w = tid >> 5;
    const int wb = w & 1, wc = w >> 1;
    const int mtile = blockIdx.x, bh = blockIdx.y;
    const float sc = scale_p[0];

    // ---- A tile load (32 rows x 128 bf16, hi+lo) via cp.async ----
    {
        int row = tid >> 4, c = tid & 15;
        size_t g = ((size_t)(bh * Pp + mtile * BM) + row) * 256 + c * 16;
        uint32_t off = row * 256 + (((c ^ (row & 7)) & 15) << 4);
        cpa16(sb + OFF_AH + off, (const char*)g_qhi + g);
        cpa16(sb + OFF_AL + off, (const char*)g_qlo + g);
    }

    auto pfB = [&](int t) {
        uint32_t dst = sb + OFF_B + (t % 3) * BBUF;
        const char* kh = (const char*)g_khi + (size_t)(bh * Pp + t * TN) * 256;
        const char* kl = (const char*)g_klo + (size_t)(bh * Pp + t * TN) * 256;
        #pragma unroll
        for (int i = 0; i < 4; ++i) {
            int idx = tid + i * 512;
            int row = idx >> 4, c = idx & 15;
            uint32_t off = row * 256 + (((c ^ (row & 7)) & 15) << 4);
            cpa16(dst + off, kh + row * 256 + c * 16);
            cpa16(dst + 32768 + off, kl + row * 256 + c * 16);
        }
        cpa_commit();
    };
    pfB(0);  // group 0 = A + B0
    pfB(1);
    pfB(2);

    // ldmatrix x4 address components: lm = which 8x8 matrix, lr = row in it
    const int lm = lane >> 3, lr = lane & 7;
    // A: m0 rows0-7/k0-7, m1 rows8-15/k0-7, m2 rows0-7/k8-15, m3 rows8-15/k8-15
    const int arow = wb * 16 + ((lm & 1) << 3) + lr;
    const uint32_t arow256 = (uint32_t)arow * 256;
    const int ax7 = arow & 7, amc = lm >> 1;    // chunk offset contribution
    // B: m0 keys0-7/k0-7, m1 keys0-7/k8-15, m2 keys8-15/k0-7, m3 keys8-15/k8-15
    const int brow = wc * 16 + ((lm >> 1) << 3) + lr;
    const uint32_t brow256 = (uint32_t)brow * 256;
    const int bx7 = brow & 7, bmc = lm & 1;

    float acc[NT][8];
    #pragma unroll
    for (int t = 0; t < NT; ++t)
        #pragma unroll
        for (int j = 0; j < 8; ++j) acc[t][j] = 0.0f;

    #pragma unroll
    for (int t = 0; t < NT; ++t) {
        if (t < 6) cpa_wait<2>(); else if (t == 6) cpa_wait<1>(); else cpa_wait<0>();
        __syncthreads();

        const uint32_t Bh = sb + OFF_B + (t % 3) * BBUF;
        const uint32_t Bl = Bh + 32768;

        #pragma unroll
        for (int ks = 0; ks < 8; ++ks) {
            uint32_t ah[4], al[4], bh4[4], bl4[4];
            uint32_t ac = (uint32_t)(((2 * ks + amc) ^ ax7) << 4);
            ldsm4(ah, sb + OFF_AH + arow256 + ac);
            ldsm4(al, sb + OFF_AL + arow256 + ac);
            uint32_t bc = (uint32_t)(((2 * ks + bmc) ^ bx7) << 4);
            ldsm4(bh4, Bh + brow256 + bc);
            ldsm4(bl4, Bl + brow256 + bc);

            mma16816(acc[t][0], acc[t][1], acc[t][2], acc[t][3], ah, bh4[0], bh4[1]);
            mma16816(acc[t][4], acc[t][5], acc[t][6], acc[t][7], ah, bh4[2], bh4[3]);
            mma16816(acc[t][0], acc[t][1], acc[t][2], acc[t][3], ah, bl4[0], bl4[1]);
            mma16816(acc[t][4], acc[t][5], acc[t][6], acc[t][7], ah, bl4[2], bl4[3]);
            mma16816(acc[t][0], acc[t][1], acc[t][2], acc[t][3], al, bh4[0], bh4[1]);
            mma16816(acc[t][4], acc[t][5], acc[t][6], acc[t][7], al, bh4[2], bh4[3]);
        }
        __syncthreads();
        if (t + 3 < NT) pfB(t + 3);
    }

    // ---- exp in place ----
    #pragma unroll
    for (int t = 0; t < NT; ++t)
        #pragma unroll
        for (int j = 0; j < 8; ++j) acc[t][j] = __expf(sc * acc[t][j]);

    // ---- row sums ----
    // per thread: rows r0 = wb*16 + lane/4 (regs j=0,1,4,5), r1 = r0+8 (j=2,3,6,7)
    float s0 = 0.0f, s1 = 0.0f;
    #pragma unroll
    for (int t = 0; t < NT; ++t) {
        s0 += (acc[t][0] + acc[t][1]) + (acc[t][4] + acc[t][5]);
        s1 += (acc[t][2] + acc[t][3]) + (acc[t][6] + acc[t][7]);
    }
    #pragma unroll
    for (int o = 1; o < 4; o <<= 1) {
        s0 += __shfl_xor_sync(0xFFFFFFFFu, s0, o);
        s1 += __shfl_xor_sync(0xFFFFFFFFu, s1, o);
    }
    float* rs  = (float*)(smem + OFF_RS);
    float* inv = (float*)(smem + OFF_INV);
    if ((lane & 3) == 0) {
        int g = lane >> 2;
        rs[wc * 32 + wb * 16 + g]     = s0;
        rs[wc * 32 + wb * 16 + 8 + g] = s1;
    }
    __syncthreads();
    if (tid < 32) {
        float tot = 0.0f;
        #pragma unroll
        for (int cb = 0; cb < 8; ++cb) tot += rs[cb * 32 + tid];
        inv[tid] = 1.0f / tot;
    }
    __syncthreads();
    const int g = lane >> 2;
    const float i0 = inv[wb * 16 + g];
    const float i1 = inv[wb * 16 + 8 + g];

    // ---- normalized stores ----
    const int r0 = mtile * BM + wb * 16 + g;
    float* ob0 = out + ((size_t)bh * Pp + r0) * Pp + wc * 16 + 2 * (lane & 3);
    float* ob1 = ob0 + 8ull * Pp;   // row r0+8
    #pragma unroll
    for (int t = 0; t < NT; ++t) {
        int c0 = t * TN;
        float2 v;
        v.x = acc[t][0] * i0; v.y = acc[t][1] * i0; *(float2*)(ob0 + c0)     = v;
        v.x = acc[t][2] * i1; v.y = acc[t][3] * i1; *(float2*)(ob1 + c0)     = v;
        v.x = acc[t][4] * i0; v.y = acc[t][5] * i0; *(float2*)(ob0 + c0 + 8) = v;
        v.x = acc[t][6] * i1; v.y = acc[t][7] * i1; *(float2*)(ob1 + c0 + 8) = v;
    }
}

// =================== launch ===================
extern "C" void kernel_launch(void* const* d_in, const int* in_sizes, int n_in,
                              void* d_out, int out_size)
{
    const float* q     = (const float*)d_in[0];
    const float* k     = (const float*)d_in[1];
    const float* scale = (const float*)d_in[2];
    float* out = (float*)d_out;

    silu_split_kernel<<<NELEM / 4 / 256, 256>>>(q, k);

    cudaFuncSetAttribute(attn_mma_kernel,
                         cudaFuncAttributeMaxDynamicSharedMemorySize, SMEM2);
    dim3 grid(Pp / BM, Bc * Hc);  // (32, 64)
    attn_mma_kernel<<<grid, 512, SMEM2>>>(scale, out);
}